// round 4
// baseline (speedup 1.0000x reference)
#include <cuda_runtime.h>
#include <cuda_bf16.h>
#include <cstdint>

#define N_NODES  100000
#define ROWSP    100096          // padded to multiple of 128
#define N_EDGES  250000
#define N_GRAPHS 512
#define EMBED    256
#define HIDDEN   512
#define HALF_H   256
#define OUT_DIM  128
#define BN_EPS   1e-5f

// ---------------- scratch (device globals; no allocation allowed) ----------
__device__ float g_h0  [(size_t)N_NODES * EMBED];
__device__ float g_agg1[(size_t)N_NODES * EMBED];
__device__ float g_y   [(size_t)N_NODES * HIDDEN];   // raw GEMM accumulators (no bias)
__device__ float g_h   [(size_t)N_NODES * HIDDEN];   // h1 (post-BN layer 1)
__device__ float g_agg2[(size_t)N_NODES * HIDDEN];
__device__ float g_stats[4 * HIDDEN];                // [layer][sum|sumsq][c]
__device__ float g_coefA[2 * HIDDEN];
__device__ float g_coefB[2 * HIDDEN];
__device__ float g_pooled[N_GRAPHS * HIDDEN];
__device__ float g_cnt[N_GRAPHS];
__device__ float g_z[N_GRAPHS * HALF_H];
// bf16 split operands for tensor-core GEMMs
__device__ __nv_bfloat16 g_Ahi[(size_t)ROWSP * HIDDEN];
__device__ __nv_bfloat16 g_Alo[(size_t)ROWSP * HIDDEN];
__device__ __nv_bfloat16 g_Wthi[HIDDEN * HIDDEN];    // [N][K] K-major
__device__ __nv_bfloat16 g_Wtlo[HIDDEN * HIDDEN];

// ---------------- PTX helpers (portable, no tcgen05) -----------------------
__device__ __forceinline__ uint32_t smem_u32(const void* p) {
    uint32_t a;
    asm("{ .reg .u64 t; cvta.to.shared.u64 t, %1; cvt.u32.u64 %0, t; }" : "=r"(a) : "l"(p));
    return a;
}
__device__ __forceinline__ void cp_async16(uint32_t dst, const void* src) {
    asm volatile("cp.async.cg.shared.global [%0], [%1], 16;" :: "r"(dst), "l"(src));
}
#define CP_COMMIT()  asm volatile("cp.async.commit_group;" ::: "memory")
#define CP_WAIT(n)   asm volatile("cp.async.wait_group %0;" :: "n"(n) : "memory")

__device__ __forceinline__ void ldm4(uint32_t* r, uint32_t addr) {
    asm volatile("ldmatrix.sync.aligned.m8n8.x4.shared.b16 {%0,%1,%2,%3}, [%4];"
                 : "=r"(r[0]), "=r"(r[1]), "=r"(r[2]), "=r"(r[3]) : "r"(addr));
}
__device__ __forceinline__ void mma_bf16(float* c, const uint32_t* a, const uint32_t* b) {
    asm volatile(
        "mma.sync.aligned.m16n8k16.row.col.f32.bf16.bf16.f32 "
        "{%0,%1,%2,%3}, {%4,%5,%6,%7}, {%8,%9}, {%0,%1,%2,%3};"
        : "+f"(c[0]), "+f"(c[1]), "+f"(c[2]), "+f"(c[3])
        : "r"(a[0]), "r"(a[1]), "r"(a[2]), "r"(a[3]), "r"(b[0]), "r"(b[1]));
}
// 16B-quad XOR swizzle within a [row][32 bf16] tile (64B rows)
__device__ __forceinline__ uint32_t swz(int row, int q) {
    return (uint32_t)(row * 64 + ((q ^ ((row >> 1) & 3)) << 4));
}

// ---------------- small kernels ---------------------------------------------
__global__ void k_gather(const int* __restrict__ x, const float* __restrict__ emb) {
    int idx = blockIdx.x * blockDim.x + threadIdx.x;
    if (idx >= N_NODES * (EMBED / 4)) return;
    int n = idx >> 6;
    int c = idx & 63;
    int tok = __ldg(&x[n]);
    float4 v = __ldg((const float4*)emb + (size_t)tok * (EMBED / 4) + c);
    ((float4*)g_h0)[idx]   = v;
    ((float4*)g_agg1)[idx] = v;
}

__global__ void k_scatter(const int* __restrict__ ei, const float* __restrict__ h,
                          float* __restrict__ agg, int c4shift) {
    long long idx = (long long)blockIdx.x * blockDim.x + threadIdx.x;
    int C4 = 1 << c4shift;
    if (idx >= (long long)N_EDGES * C4) return;
    int e = (int)(idx >> c4shift);
    int c = (int)(idx & (C4 - 1));
    int s = __ldg(&ei[e]);
    int d = __ldg(&ei[N_EDGES + e]);
    float4 v = __ldg((const float4*)h + (long long)s * C4 + c);
    float4* p = (float4*)agg + (long long)d * C4 + c;
    asm volatile("red.global.add.v4.f32 [%0], {%1,%2,%3,%4};"
                 :: "l"(p), "f"(v.x), "f"(v.y), "f"(v.z), "f"(v.w) : "memory");
}

__global__ void k_finalize(const float* __restrict__ stats, const float* __restrict__ g,
                           const float* __restrict__ be,
                           float* __restrict__ coefA, float* __restrict__ coefB) {
    int c = threadIdx.x;
    float inv_n = 1.f / (float)N_NODES;
    float mu  = stats[c] * inv_n;
    float var = fmaxf(stats[HIDDEN + c] * inv_n - mu * mu, 0.f);
    float sc  = rsqrtf(var + BN_EPS) * g[c];
    coefA[c] = sc;
    coefB[c] = be[c] - mu * sc;
}

__global__ void k_norm_relu(const float* __restrict__ Y, const float* __restrict__ coefA,
                            const float* __restrict__ coefB, float* __restrict__ H,
                            float* __restrict__ Hcopy) {
    long long idx = (long long)blockIdx.x * blockDim.x + threadIdx.x;
    if (idx >= (long long)N_NODES * (HIDDEN / 4)) return;
    int c = (int)(idx & (HIDDEN / 4 - 1));
    float4 v = ((const float4*)Y)[idx];
    float4 a = __ldg((const float4*)coefA + c);
    float4 b = __ldg((const float4*)coefB + c);
    float4 o;
    o.x = fmaxf(v.x * a.x + b.x, 0.f);
    o.y = fmaxf(v.y * a.y + b.y, 0.f);
    o.z = fmaxf(v.z * a.z + b.z, 0.f);
    o.w = fmaxf(v.w * a.w + b.w, 0.f);
    ((float4*)H)[idx] = o;
    if (Hcopy) ((float4*)Hcopy)[idx] = o;
}

// pooling fused with layer-2 BN + ReLU: reads raw y2, applies coef inline
__global__ void k_pool_bn(const float* __restrict__ Y, const int* __restrict__ batch,
                          const float* __restrict__ cA, const float* __restrict__ cB) {
    const int NPB = 256;
    __shared__ int sb[NPB];
    int t     = threadIdx.x;
    int start = blockIdx.x * NPB;
    int end   = min(start + NPB, N_NODES);
    int n     = end - start;
    if (n <= 0) return;
    for (int i = t; i < n; i += 512) sb[i] = batch[start + i];
    __syncthreads();
    float a = __ldg(&cA[t]);
    float b = __ldg(&cB[t]);
    float acc = 0.f;
    int cur = sb[0], run = 0;
    for (int i = 0; i < n; i++) {
        int bg = sb[i];
        if (bg != cur) {
            atomicAdd(&g_pooled[(size_t)cur * HIDDEN + t], acc);
            if (t == 0) atomicAdd(&g_cnt[cur], (float)run);
            acc = 0.f; run = 0; cur = bg;
        }
        acc += fmaxf(fmaf(Y[(long long)(start + i) * HIDDEN + t], a, b), 0.f);
        run++;
    }
    atomicAdd(&g_pooled[(size_t)cur * HIDDEN + t], acc);
    if (t == 0) atomicAdd(&g_cnt[cur], (float)run);
}

__global__ void k_lin1(const float* __restrict__ Wl1, const float* __restrict__ bl1) {
    __shared__ float ps[HIDDEN];
    int g = blockIdx.x, j = threadIdx.x;
    ps[j]       = g_pooled[(size_t)g * HIDDEN + j];
    ps[j + 256] = g_pooled[(size_t)g * HIDDEN + j + 256];
    __syncthreads();
    float inv = 1.f / fmaxf(g_cnt[g], 1.f);
    float acc = 0.f;
#pragma unroll 8
    for (int k = 0; k < HIDDEN; k++)
        acc += ps[k] * __ldg(&Wl1[(size_t)k * HALF_H + j]);
    g_z[(size_t)g * HALF_H + j] = fmaxf(acc * inv + bl1[j], 0.f);
}

__global__ void k_lin2(const float* __restrict__ Wl2, const float* __restrict__ bl2,
                       float* __restrict__ out) {
    __shared__ float zs[HALF_H];
    int g = blockIdx.x, j = threadIdx.x;
    zs[j]       = g_z[(size_t)g * HALF_H + j];
    zs[j + 128] = g_z[(size_t)g * HALF_H + j + 128];
    __syncthreads();
    float acc = bl2[j];
#pragma unroll 8
    for (int k = 0; k < HALF_H; k++)
        acc += zs[k] * __ldg(&Wl2[(size_t)k * OUT_DIM + j]);
    out[(size_t)g * OUT_DIM + j] = acc;
}

// ---------------- bf16 split kernels ----------------------------------------
__global__ void k_split_A(const float* __restrict__ A, int rows, int kshift,
                          __nv_bfloat16* __restrict__ Ahi, __nv_bfloat16* __restrict__ Alo) {
    int K = 1 << kshift;
    long long idx = (long long)blockIdx.x * blockDim.x + threadIdx.x;  // float4 units
    if (idx >= (long long)ROWSP * (K >> 2)) return;
    int r = (int)(idx >> (kshift - 2));
    float4 v = (r < rows) ? __ldg((const float4*)A + idx) : make_float4(0.f, 0.f, 0.f, 0.f);
    float f[4] = {v.x, v.y, v.z, v.w};
    __nv_bfloat16 h0 = __float2bfloat16_rn(f[0]);
    __nv_bfloat16 h1 = __float2bfloat16_rn(f[1]);
    __nv_bfloat16 h2 = __float2bfloat16_rn(f[2]);
    __nv_bfloat16 h3 = __float2bfloat16_rn(f[3]);
    __nv_bfloat162 hi0(h0, h1), hi1(h2, h3);
    __nv_bfloat162 lo0(__float2bfloat16_rn(f[0] - __bfloat162float(h0)),
                       __float2bfloat16_rn(f[1] - __bfloat162float(h1)));
    __nv_bfloat162 lo1(__float2bfloat16_rn(f[2] - __bfloat162float(h2)),
                       __float2bfloat16_rn(f[3] - __bfloat162float(h3)));
    ((__nv_bfloat162*)Ahi)[idx * 2]     = hi0;
    ((__nv_bfloat162*)Ahi)[idx * 2 + 1] = hi1;
    ((__nv_bfloat162*)Alo)[idx * 2]     = lo0;
    ((__nv_bfloat162*)Alo)[idx * 2 + 1] = lo1;
}

__global__ void k_split_W(const float* __restrict__ W, int kshift,
                          __nv_bfloat16* __restrict__ Wthi, __nv_bfloat16* __restrict__ Wtlo) {
    int K = 1 << kshift;
    int idx = blockIdx.x * blockDim.x + threadIdx.x;
    if (idx >= HIDDEN * K) return;
    int n = idx >> kshift;
    int k = idx & (K - 1);
    float v = __ldg(&W[(size_t)k * HIDDEN + n]);
    __nv_bfloat16 hi = __float2bfloat16_rn(v);
    Wthi[idx] = hi;
    Wtlo[idx] = __float2bfloat16_rn(v - __bfloat162float(hi));
}

// ---------------- mma.sync bf16x3 GEMM + fused BN stats ----------------------
// C[ROWSP x 512] = (Ahi+Alo)[ROWSP x K] @ (Wthi+Wtlo)^T  (NO bias; BN absorbs it)
// CTA: 128(M) x 128(N), K-chunk 32, 4-stage cp.async pipeline, 1 sync/chunk.
// Epilogue: store acc + accumulate per-column sum/sumsq into stats[].
#define GT       256
#define OFF_AHI  0
#define OFF_ALO  8192
#define OFF_BHI  16384
#define OFF_BLO  24576
#define STAGE    32768
#define NSTAGE   4
#define G_SMEM   (NSTAGE * STAGE)

__global__ __launch_bounds__(GT)
void k_mma_gemm(const __nv_bfloat16* __restrict__ Ahi, const __nv_bfloat16* __restrict__ Alo,
                const __nv_bfloat16* __restrict__ Bhi, const __nv_bfloat16* __restrict__ Blo,
                float* __restrict__ C, float* __restrict__ stats, int K) {
    extern __shared__ char smem[];
    __shared__ float ss[128];
    __shared__ float qq[128];
    uint32_t sb = smem_u32(smem);
    int tid  = threadIdx.x;
    int lane = tid & 31;
    int wid  = tid >> 5;
    int wm   = (wid & 3) * 32;   // warp M offset (4 warps in M)
    int wn   = (wid >> 2) * 64;  // warp N offset (2 warps in N)
    int row0 = blockIdx.y * 128;
    int col0 = blockIdx.x * 128;

    if (tid < 128) { ss[tid] = 0.f; qq[tid] = 0.f; }

    float acc[2][8][4];
#pragma unroll
    for (int i = 0; i < 2; i++)
#pragma unroll
        for (int j = 0; j < 8; j++)
#pragma unroll
            for (int l = 0; l < 4; l++) acc[i][j][l] = 0.f;

    int nch = K >> 5;

    auto load_chunk = [&](int i) {
        int k0 = i << 5;
        uint32_t base = sb + (i & (NSTAGE - 1)) * STAGE;
#pragma unroll
        for (int p = 0; p < 2; p++) {
            int u = tid + p * GT;          // 0..511
            int r = u >> 2, q = u & 3;
            uint32_t so = swz(r, q);
            size_t ga = (size_t)(row0 + r) * K + k0 + q * 8;
            size_t gb = (size_t)(col0 + r) * K + k0 + q * 8;
            cp_async16(base + OFF_AHI + so, Ahi + ga);
            cp_async16(base + OFF_ALO + so, Alo + ga);
            cp_async16(base + OFF_BHI + so, Bhi + gb);
            cp_async16(base + OFF_BLO + so, Blo + gb);
        }
    };

    load_chunk(0); CP_COMMIT();
    load_chunk(1); CP_COMMIT();

    // lane-derived ldmatrix address components
    int a_row = (lane & 15);
    int a_qh  = (lane >> 4);
    int b_row = (lane & 7) + ((lane >> 4) << 3);
    int b_qh  = (lane >> 3) & 1;

    for (int i = 0; i < nch; i++) {
        // issue prefetch of chunk i+2 into a buffer idle since iter i-2
        if (i + 2 < nch) load_chunk(i + 2);
        CP_COMMIT();                        // empty group at tail — keeps count
        CP_WAIT(2);                         // chunk i landed (2 newest may fly)
        __syncthreads();
        uint32_t stg = sb + (i & (NSTAGE - 1)) * STAGE;

#pragma unroll
        for (int s = 0; s < 2; s++) {
            uint32_t ah[2][4], al[2][4];
#pragma unroll
            for (int mt = 0; mt < 2; mt++) {
                int r = wm + mt * 16 + a_row;
                int q = a_qh + 2 * s;
                ldm4(ah[mt], stg + OFF_AHI + swz(r, q));
                ldm4(al[mt], stg + OFF_ALO + swz(r, q));
            }
#pragma unroll
            for (int pr = 0; pr < 4; pr++) {
                int r = wn + pr * 16 + b_row;
                int q = b_qh + 2 * s;
                uint32_t bh[4], bl[4];
                ldm4(bh, stg + OFF_BHI + swz(r, q));
                ldm4(bl, stg + OFF_BLO + swz(r, q));
#pragma unroll
                for (int mt = 0; mt < 2; mt++) {
#pragma unroll
                    for (int h = 0; h < 2; h++) {
                        float* c = acc[mt][pr * 2 + h];
                        mma_bf16(c, ah[mt], bh + 2 * h);
                        mma_bf16(c, ah[mt], bl + 2 * h);
                        mma_bf16(c, al[mt], bh + 2 * h);
                    }
                }
            }
        }
    }

    // ---- epilogue: store raw acc + column stats
    int g   = lane >> 2;
    int tig = lane & 3;
#pragma unroll
    for (int mt = 0; mt < 2; mt++) {
        int r0 = row0 + wm + mt * 16 + g;
        int r1 = r0 + 8;
#pragma unroll
        for (int nt = 0; nt < 8; nt++) {
            int col = col0 + wn + nt * 8 + 2 * tig;
            if (r0 < N_NODES) {
                float2 o{acc[mt][nt][0], acc[mt][nt][1]};
                *(float2*)(C + (size_t)r0 * HIDDEN + col) = o;
            }
            if (r1 < N_NODES) {
                float2 o{acc[mt][nt][2], acc[mt][nt][3]};
                *(float2*)(C + (size_t)r1 * HIDDEN + col) = o;
            }
        }
    }
    // per-column sum / sumsq (pad rows contribute exact zeros)
#pragma unroll
    for (int nt = 0; nt < 8; nt++) {
        float s0 = 0.f, q0 = 0.f, s1 = 0.f, q1 = 0.f;
#pragma unroll
        for (int mt = 0; mt < 2; mt++) {
            float c0 = acc[mt][nt][0], c1 = acc[mt][nt][1];
            float c2 = acc[mt][nt][2], c3 = acc[mt][nt][3];
            s0 += c0 + c2;  q0 += c0 * c0 + c2 * c2;
            s1 += c1 + c3;  q1 += c1 * c1 + c3 * c3;
        }
#pragma unroll
        for (int o = 4; o < 32; o <<= 1) {
            s0 += __shfl_xor_sync(0xFFFFFFFF, s0, o);
            q0 += __shfl_xor_sync(0xFFFFFFFF, q0, o);
            s1 += __shfl_xor_sync(0xFFFFFFFF, s1, o);
            q1 += __shfl_xor_sync(0xFFFFFFFF, q1, o);
        }
        if (lane < 4) {
            int c = wn + nt * 8 + 2 * lane;   // lane == tig here (g==0)
            atomicAdd(&ss[c], s0);     atomicAdd(&qq[c], q0);
            atomicAdd(&ss[c + 1], s1); atomicAdd(&qq[c + 1], q1);
        }
    }
    __syncthreads();
    if (tid < 128) {
        atomicAdd(&stats[col0 + tid], ss[tid]);
        atomicAdd(&stats[HIDDEN + col0 + tid], qq[tid]);
    }
}

// ---------------- launch ----------------------------------------------------
extern "C" void kernel_launch(void* const* d_in, const int* in_sizes, int n_in,
                              void* d_out, int out_size) {
    const int*   x     = (const int*)d_in[0];
    const int*   ei    = (const int*)d_in[1];
    const int*   batch = (const int*)d_in[2];
    const float* emb   = (const float*)d_in[3];
    const float* W1    = (const float*)d_in[4];
    const float* g1    = (const float*)d_in[6];
    const float* be1   = (const float*)d_in[7];
    const float* W2    = (const float*)d_in[8];
    const float* g2    = (const float*)d_in[10];
    const float* be2   = (const float*)d_in[11];
    const float* Wl1   = (const float*)d_in[12];
    const float* bl1   = (const float*)d_in[13];
    const float* Wl2   = (const float*)d_in[14];
    const float* bl2   = (const float*)d_in[15];
    float* out = (float*)d_out;

    cudaFuncSetAttribute(k_mma_gemm, cudaFuncAttributeMaxDynamicSharedMemorySize, G_SMEM);

    float *p_h0, *p_agg1, *p_y, *p_h, *p_agg2, *p_stats, *p_coefA, *p_coefB, *p_pooled, *p_cnt;
    __nv_bfloat16 *p_Ahi, *p_Alo, *p_Wthi, *p_Wtlo;
    cudaGetSymbolAddress((void**)&p_h0,    g_h0);
    cudaGetSymbolAddress((void**)&p_agg1,  g_agg1);
    cudaGetSymbolAddress((void**)&p_y,     g_y);
    cudaGetSymbolAddress((void**)&p_h,     g_h);
    cudaGetSymbolAddress((void**)&p_agg2,  g_agg2);
    cudaGetSymbolAddress((void**)&p_stats, g_stats);
    cudaGetSymbolAddress((void**)&p_coefA, g_coefA);
    cudaGetSymbolAddress((void**)&p_coefB, g_coefB);
    cudaGetSymbolAddress((void**)&p_pooled,g_pooled);
    cudaGetSymbolAddress((void**)&p_cnt,   g_cnt);
    cudaGetSymbolAddress((void**)&p_Ahi,   g_Ahi);
    cudaGetSymbolAddress((void**)&p_Alo,   g_Alo);
    cudaGetSymbolAddress((void**)&p_Wthi,  g_Wthi);
    cudaGetSymbolAddress((void**)&p_Wtlo,  g_Wtlo);

    cudaMemsetAsync(p_stats,  0, 4 * HIDDEN * sizeof(float));
    cudaMemsetAsync(p_pooled, 0, (size_t)N_GRAPHS * HIDDEN * sizeof(float));
    cudaMemsetAsync(p_cnt,    0, N_GRAPHS * sizeof(float));

    // ---- embedding + layer-1 aggregation
    k_gather<<<(N_NODES * (EMBED / 4) + 255) / 256, 256>>>(x, emb);
    {
        long long tot = (long long)N_EDGES * (EMBED / 4);
        k_scatter<<<(int)((tot + 255) / 256), 256>>>(ei, p_h0, p_agg1, 6);
    }
    // ---- GEMM1 (fused BN stats)
    {
        long long tot = (long long)ROWSP * (EMBED / 4);
        k_split_A<<<(int)((tot + 255) / 256), 256>>>(p_agg1, N_NODES, 8, p_Ahi, p_Alo);
        k_split_W<<<(HIDDEN * EMBED + 255) / 256, 256>>>(W1, 8, p_Wthi, p_Wtlo);
        dim3 grid(HIDDEN / 128, ROWSP / 128);
        k_mma_gemm<<<grid, GT, G_SMEM>>>(p_Ahi, p_Alo, p_Wthi, p_Wtlo, p_y, p_stats, EMBED);
    }
    k_finalize<<<1, HIDDEN>>>(p_stats, g1, be1, p_coefA, p_coefB);
    {
        long long tot = (long long)N_NODES * (HIDDEN / 4);
        k_norm_relu<<<(int)((tot + 255) / 256), 256>>>(p_y, p_coefA, p_coefB, p_h, p_agg2);
    }

    // ---- layer-2 aggregation
    {
        long long tot = (long long)N_EDGES * (HIDDEN / 4);
        k_scatter<<<(int)((tot + 255) / 256), 256>>>(ei, p_h, p_agg2, 7);
    }
    // ---- GEMM2 (fused BN stats)
    {
        long long tot = (long long)ROWSP * (HIDDEN / 4);
        k_split_A<<<(int)((tot + 255) / 256), 256>>>(p_agg2, N_NODES, 9, p_Ahi, p_Alo);
        k_split_W<<<(HIDDEN * HIDDEN + 255) / 256, 256>>>(W2, 9, p_Wthi, p_Wtlo);
        dim3 grid(HIDDEN / 128, ROWSP / 128);
        k_mma_gemm<<<grid, GT, G_SMEM>>>(p_Ahi, p_Alo, p_Wthi, p_Wtlo, p_y,
                                         p_stats + 2 * HIDDEN, HIDDEN);
    }
    k_finalize<<<1, HIDDEN>>>(p_stats + 2 * HIDDEN, g2, be2,
                              p_coefA + HIDDEN, p_coefB + HIDDEN);

    // ---- pooling (fused layer-2 BN+ReLU) + head
    k_pool_bn<<<(N_NODES + 255) / 256, 512>>>(p_y, batch, p_coefA + HIDDEN, p_coefB + HIDDEN);
    k_lin1<<<N_GRAPHS, HALF_H>>>(Wl1, bl1);
    k_lin2<<<N_GRAPHS, OUT_DIM>>>(Wl2, bl2, out);
}

// round 5
// speedup vs baseline: 1.1006x; 1.1006x over previous
#include <cuda_runtime.h>
#include <cuda_bf16.h>
#include <cstdint>

#define N_NODES  100000
#define ROWSP    100096          // padded to multiple of 128
#define N_EDGES  250000
#define N_GRAPHS 512
#define EMBED    256
#define HIDDEN   512
#define HALF_H   256
#define OUT_DIM  128
#define BN_EPS   1e-5f

// ---------------- scratch (device globals; no allocation allowed) ----------
__device__ float g_h0  [(size_t)N_NODES * EMBED];
__device__ float g_agg1[(size_t)N_NODES * EMBED];
__device__ float g_y   [(size_t)N_NODES * HIDDEN];   // raw GEMM accumulators (no bias)
__device__ float g_h   [(size_t)N_NODES * HIDDEN];   // h1 (post-BN layer 1)
__device__ float g_agg2[(size_t)N_NODES * HIDDEN];
__device__ float g_stats[4 * HIDDEN];                // [layer][sum|sumsq][c]
__device__ float g_coefA[2 * HIDDEN];
__device__ float g_coefB[2 * HIDDEN];
__device__ float g_pooled[N_GRAPHS * HIDDEN];
__device__ float g_cnt[N_GRAPHS];
__device__ float g_z[N_GRAPHS * HALF_H];
// bf16 split operands for tensor-core GEMMs
__device__ __nv_bfloat16 g_Ahi[(size_t)ROWSP * HIDDEN];
__device__ __nv_bfloat16 g_Alo[(size_t)ROWSP * HIDDEN];
__device__ __nv_bfloat16 g_Wthi[HIDDEN * HIDDEN];    // [N][K] K-major
__device__ __nv_bfloat16 g_Wtlo[HIDDEN * HIDDEN];

// ---------------- PTX helpers (portable, no tcgen05) -----------------------
__device__ __forceinline__ uint32_t smem_u32(const void* p) {
    uint32_t a;
    asm("{ .reg .u64 t; cvta.to.shared.u64 t, %1; cvt.u32.u64 %0, t; }" : "=r"(a) : "l"(p));
    return a;
}
__device__ __forceinline__ void cp_async16(uint32_t dst, const void* src) {
    asm volatile("cp.async.cg.shared.global [%0], [%1], 16;" :: "r"(dst), "l"(src));
}
#define CP_COMMIT()  asm volatile("cp.async.commit_group;" ::: "memory")
#define CP_WAIT(n)   asm volatile("cp.async.wait_group %0;" :: "n"(n) : "memory")

__device__ __forceinline__ void ldm4(uint32_t* r, uint32_t addr) {
    asm volatile("ldmatrix.sync.aligned.m8n8.x4.shared.b16 {%0,%1,%2,%3}, [%4];"
                 : "=r"(r[0]), "=r"(r[1]), "=r"(r[2]), "=r"(r[3]) : "r"(addr));
}
__device__ __forceinline__ void mma_bf16(float* c, const uint32_t* a, const uint32_t* b) {
    asm volatile(
        "mma.sync.aligned.m16n8k16.row.col.f32.bf16.bf16.f32 "
        "{%0,%1,%2,%3}, {%4,%5,%6,%7}, {%8,%9}, {%0,%1,%2,%3};"
        : "+f"(c[0]), "+f"(c[1]), "+f"(c[2]), "+f"(c[3])
        : "r"(a[0]), "r"(a[1]), "r"(a[2]), "r"(a[3]), "r"(b[0]), "r"(b[1]));
}
// 16B-quad XOR swizzle within a [row][32 bf16] tile (64B rows)
__device__ __forceinline__ uint32_t swz(int row, int q) {
    return (uint32_t)(row * 64 + ((q ^ ((row >> 1) & 3)) << 4));
}

// ---------------- small kernels ---------------------------------------------
__global__ void k_gather(const int* __restrict__ x, const float* __restrict__ emb) {
    int idx = blockIdx.x * blockDim.x + threadIdx.x;
    if (idx >= N_NODES * (EMBED / 4)) return;
    int n = idx >> 6;
    int c = idx & 63;
    int tok = __ldg(&x[n]);
    float4 v = __ldg((const float4*)emb + (size_t)tok * (EMBED / 4) + c);
    ((float4*)g_h0)[idx]   = v;
    ((float4*)g_agg1)[idx] = v;
}

__global__ void k_scatter(const int* __restrict__ ei, const float* __restrict__ h,
                          float* __restrict__ agg, int c4shift) {
    long long idx = (long long)blockIdx.x * blockDim.x + threadIdx.x;
    int C4 = 1 << c4shift;
    if (idx >= (long long)N_EDGES * C4) return;
    int e = (int)(idx >> c4shift);
    int c = (int)(idx & (C4 - 1));
    int s = __ldg(&ei[e]);
    int d = __ldg(&ei[N_EDGES + e]);
    float4 v = __ldg((const float4*)h + (long long)s * C4 + c);
    float4* p = (float4*)agg + (long long)d * C4 + c;
    asm volatile("red.global.add.v4.f32 [%0], {%1,%2,%3,%4};"
                 :: "l"(p), "f"(v.x), "f"(v.y), "f"(v.z), "f"(v.w) : "memory");
}

__global__ void k_finalize(const float* __restrict__ stats, const float* __restrict__ g,
                           const float* __restrict__ be,
                           float* __restrict__ coefA, float* __restrict__ coefB) {
    int c = threadIdx.x;
    float inv_n = 1.f / (float)N_NODES;
    float mu  = stats[c] * inv_n;
    float var = fmaxf(stats[HIDDEN + c] * inv_n - mu * mu, 0.f);
    float sc  = rsqrtf(var + BN_EPS) * g[c];
    coefA[c] = sc;
    coefB[c] = be[c] - mu * sc;
}

__global__ void k_norm_relu(const float* __restrict__ Y, const float* __restrict__ coefA,
                            const float* __restrict__ coefB, float* __restrict__ H,
                            float* __restrict__ Hcopy) {
    long long idx = (long long)blockIdx.x * blockDim.x + threadIdx.x;
    if (idx >= (long long)N_NODES * (HIDDEN / 4)) return;
    int c = (int)(idx & (HIDDEN / 4 - 1));
    float4 v = ((const float4*)Y)[idx];
    float4 a = __ldg((const float4*)coefA + c);
    float4 b = __ldg((const float4*)coefB + c);
    float4 o;
    o.x = fmaxf(v.x * a.x + b.x, 0.f);
    o.y = fmaxf(v.y * a.y + b.y, 0.f);
    o.z = fmaxf(v.z * a.z + b.z, 0.f);
    o.w = fmaxf(v.w * a.w + b.w, 0.f);
    ((float4*)H)[idx] = o;
    if (Hcopy) ((float4*)Hcopy)[idx] = o;
}

// pooling fused with layer-2 BN + ReLU: reads raw y2, applies coef inline
__global__ void k_pool_bn(const float* __restrict__ Y, const int* __restrict__ batch,
                          const float* __restrict__ cA, const float* __restrict__ cB) {
    const int NPB = 256;
    __shared__ int sb[NPB];
    int t     = threadIdx.x;
    int start = blockIdx.x * NPB;
    int end   = min(start + NPB, N_NODES);
    int n     = end - start;
    if (n <= 0) return;
    for (int i = t; i < n; i += 512) sb[i] = batch[start + i];
    __syncthreads();
    float a = __ldg(&cA[t]);
    float b = __ldg(&cB[t]);
    float acc = 0.f;
    int cur = sb[0], run = 0;
    for (int i = 0; i < n; i++) {
        int bg = sb[i];
        if (bg != cur) {
            atomicAdd(&g_pooled[(size_t)cur * HIDDEN + t], acc);
            if (t == 0) atomicAdd(&g_cnt[cur], (float)run);
            acc = 0.f; run = 0; cur = bg;
        }
        acc += fmaxf(fmaf(Y[(long long)(start + i) * HIDDEN + t], a, b), 0.f);
        run++;
    }
    atomicAdd(&g_pooled[(size_t)cur * HIDDEN + t], acc);
    if (t == 0) atomicAdd(&g_cnt[cur], (float)run);
}

__global__ void k_lin1(const float* __restrict__ Wl1, const float* __restrict__ bl1) {
    __shared__ float ps[HIDDEN];
    int g = blockIdx.x, j = threadIdx.x;
    ps[j]       = g_pooled[(size_t)g * HIDDEN + j];
    ps[j + 256] = g_pooled[(size_t)g * HIDDEN + j + 256];
    __syncthreads();
    float inv = 1.f / fmaxf(g_cnt[g], 1.f);
    float acc = 0.f;
#pragma unroll 8
    for (int k = 0; k < HIDDEN; k++)
        acc += ps[k] * __ldg(&Wl1[(size_t)k * HALF_H + j]);
    g_z[(size_t)g * HALF_H + j] = fmaxf(acc * inv + bl1[j], 0.f);
}

__global__ void k_lin2(const float* __restrict__ Wl2, const float* __restrict__ bl2,
                       float* __restrict__ out) {
    __shared__ float zs[HALF_H];
    int g = blockIdx.x, j = threadIdx.x;
    zs[j]       = g_z[(size_t)g * HALF_H + j];
    zs[j + 128] = g_z[(size_t)g * HALF_H + j + 128];
    __syncthreads();
    float acc = bl2[j];
#pragma unroll 8
    for (int k = 0; k < HALF_H; k++)
        acc += zs[k] * __ldg(&Wl2[(size_t)k * OUT_DIM + j]);
    out[(size_t)g * OUT_DIM + j] = acc;
}

// ---------------- bf16 split kernels ----------------------------------------
__global__ void k_split_A(const float* __restrict__ A, int rows, int kshift,
                          __nv_bfloat16* __restrict__ Ahi, __nv_bfloat16* __restrict__ Alo) {
    int K = 1 << kshift;
    long long idx = (long long)blockIdx.x * blockDim.x + threadIdx.x;  // float4 units
    if (idx >= (long long)ROWSP * (K >> 2)) return;
    int r = (int)(idx >> (kshift - 2));
    float4 v = (r < rows) ? __ldg((const float4*)A + idx) : make_float4(0.f, 0.f, 0.f, 0.f);
    float f[4] = {v.x, v.y, v.z, v.w};
    __nv_bfloat16 h0 = __float2bfloat16_rn(f[0]);
    __nv_bfloat16 h1 = __float2bfloat16_rn(f[1]);
    __nv_bfloat16 h2 = __float2bfloat16_rn(f[2]);
    __nv_bfloat16 h3 = __float2bfloat16_rn(f[3]);
    __nv_bfloat162 hi0(h0, h1), hi1(h2, h3);
    __nv_bfloat162 lo0(__float2bfloat16_rn(f[0] - __bfloat162float(h0)),
                       __float2bfloat16_rn(f[1] - __bfloat162float(h1)));
    __nv_bfloat162 lo1(__float2bfloat16_rn(f[2] - __bfloat162float(h2)),
                       __float2bfloat16_rn(f[3] - __bfloat162float(h3)));
    ((__nv_bfloat162*)Ahi)[idx * 2]     = hi0;
    ((__nv_bfloat162*)Ahi)[idx * 2 + 1] = hi1;
    ((__nv_bfloat162*)Alo)[idx * 2]     = lo0;
    ((__nv_bfloat162*)Alo)[idx * 2 + 1] = lo1;
}

__global__ void k_split_W(const float* __restrict__ W, int kshift,
                          __nv_bfloat16* __restrict__ Wthi, __nv_bfloat16* __restrict__ Wtlo) {
    int K = 1 << kshift;
    int idx = blockIdx.x * blockDim.x + threadIdx.x;
    if (idx >= HIDDEN * K) return;
    int n = idx >> kshift;
    int k = idx & (K - 1);
    float v = __ldg(&W[(size_t)k * HIDDEN + n]);
    __nv_bfloat16 hi = __float2bfloat16_rn(v);
    Wthi[idx] = hi;
    Wtlo[idx] = __float2bfloat16_rn(v - __bfloat162float(hi));
}

// ---------------- mma.sync bf16x3 GEMM + fused BN stats ----------------------
// C[ROWSP x 512] = (Ahi+Alo)[ROWSP x K] @ (Wthi+Wtlo)^T  (NO bias; BN absorbs it)
// CTA: 128(M) x 128(N), K-chunk 32, 2-stage double buffer (round-3 proven),
// epilogue stores raw acc + per-column sum/sumsq into stats[].
#define GT       256
#define OFF_AHI  0
#define OFF_ALO  8192
#define OFF_BHI  16384
#define OFF_BLO  24576
#define STAGE    32768
#define G_SMEM   (2 * STAGE)

__global__ __launch_bounds__(GT)
void k_mma_gemm(const __nv_bfloat16* __restrict__ Ahi, const __nv_bfloat16* __restrict__ Alo,
                const __nv_bfloat16* __restrict__ Bhi, const __nv_bfloat16* __restrict__ Blo,
                float* __restrict__ C, float* __restrict__ stats, int K) {
    extern __shared__ char smem[];
    __shared__ float ss[128];
    __shared__ float qq[128];
    uint32_t sb = smem_u32(smem);
    int tid  = threadIdx.x;
    int lane = tid & 31;
    int wid  = tid >> 5;
    int wm   = (wid & 3) * 32;   // warp M offset (4 warps in M)
    int wn   = (wid >> 2) * 64;  // warp N offset (2 warps in N)
    int row0 = blockIdx.y * 128;
    int col0 = blockIdx.x * 128;

    if (tid < 128) { ss[tid] = 0.f; qq[tid] = 0.f; }

    float acc[2][8][4];
#pragma unroll
    for (int i = 0; i < 2; i++)
#pragma unroll
        for (int j = 0; j < 8; j++)
#pragma unroll
            for (int l = 0; l < 4; l++) acc[i][j][l] = 0.f;

    int nch = K >> 5;

    auto load_chunk = [&](int i, int buf) {
        int k0 = i << 5;
        uint32_t base = sb + buf * STAGE;
#pragma unroll
        for (int p = 0; p < 2; p++) {
            int u = tid + p * GT;          // 0..511
            int r = u >> 2, q = u & 3;
            uint32_t so = swz(r, q);
            size_t ga = (size_t)(row0 + r) * K + k0 + q * 8;
            size_t gb = (size_t)(col0 + r) * K + k0 + q * 8;
            cp_async16(base + OFF_AHI + so, Ahi + ga);
            cp_async16(base + OFF_ALO + so, Alo + ga);
            cp_async16(base + OFF_BHI + so, Bhi + gb);
            cp_async16(base + OFF_BLO + so, Blo + gb);
        }
    };

    load_chunk(0, 0);
    CP_COMMIT();

    // lane-derived ldmatrix address components
    int a_row = (lane & 15);
    int a_qh  = (lane >> 4);
    int b_row = (lane & 7) + ((lane >> 4) << 3);
    int b_qh  = (lane >> 3) & 1;

    for (int i = 0; i < nch; i++) {
        if (i + 1 < nch) {
            load_chunk(i + 1, (i + 1) & 1);
            CP_COMMIT();
            CP_WAIT(1);
        } else {
            CP_WAIT(0);
        }
        __syncthreads();
        uint32_t stg = sb + (i & 1) * STAGE;

#pragma unroll
        for (int s = 0; s < 2; s++) {
            uint32_t ah[2][4], al[2][4];
#pragma unroll
            for (int mt = 0; mt < 2; mt++) {
                int r = wm + mt * 16 + a_row;
                int q = a_qh + 2 * s;
                ldm4(ah[mt], stg + OFF_AHI + swz(r, q));
                ldm4(al[mt], stg + OFF_ALO + swz(r, q));
            }
#pragma unroll
            for (int pr = 0; pr < 4; pr++) {
                int r = wn + pr * 16 + b_row;
                int q = b_qh + 2 * s;
                uint32_t bh[4], bl[4];
                ldm4(bh, stg + OFF_BHI + swz(r, q));
                ldm4(bl, stg + OFF_BLO + swz(r, q));
#pragma unroll
                for (int mt = 0; mt < 2; mt++) {
#pragma unroll
                    for (int h = 0; h < 2; h++) {
                        float* c = acc[mt][pr * 2 + h];
                        mma_bf16(c, ah[mt], bh + 2 * h);
                        mma_bf16(c, ah[mt], bl + 2 * h);
                        mma_bf16(c, al[mt], bh + 2 * h);
                    }
                }
            }
        }
        __syncthreads();
    }

    // ---- epilogue: store raw acc + column stats
    int g   = lane >> 2;
    int tig = lane & 3;
#pragma unroll
    for (int mt = 0; mt < 2; mt++) {
        int r0 = row0 + wm + mt * 16 + g;
        int r1 = r0 + 8;
#pragma unroll
        for (int nt = 0; nt < 8; nt++) {
            int col = col0 + wn + nt * 8 + 2 * tig;
            if (r0 < N_NODES) {
                float2 o{acc[mt][nt][0], acc[mt][nt][1]};
                *(float2*)(C + (size_t)r0 * HIDDEN + col) = o;
            }
            if (r1 < N_NODES) {
                float2 o{acc[mt][nt][2], acc[mt][nt][3]};
                *(float2*)(C + (size_t)r1 * HIDDEN + col) = o;
            }
        }
    }
    // per-column sum / sumsq (pad rows contribute exact zeros)
#pragma unroll
    for (int nt = 0; nt < 8; nt++) {
        float s0 = 0.f, q0 = 0.f, s1 = 0.f, q1 = 0.f;
#pragma unroll
        for (int mt = 0; mt < 2; mt++) {
            float c0 = acc[mt][nt][0], c1 = acc[mt][nt][1];
            float c2 = acc[mt][nt][2], c3 = acc[mt][nt][3];
            s0 += c0 + c2;  q0 += c0 * c0 + c2 * c2;
            s1 += c1 + c3;  q1 += c1 * c1 + c3 * c3;
        }
#pragma unroll
        for (int o = 4; o < 32; o <<= 1) {
            s0 += __shfl_xor_sync(0xFFFFFFFF, s0, o);
            q0 += __shfl_xor_sync(0xFFFFFFFF, q0, o);
            s1 += __shfl_xor_sync(0xFFFFFFFF, s1, o);
            q1 += __shfl_xor_sync(0xFFFFFFFF, q1, o);
        }
        if (lane < 4) {
            int c = wn + nt * 8 + 2 * lane;
            atomicAdd(&ss[c], s0);     atomicAdd(&qq[c], q0);
            atomicAdd(&ss[c + 1], s1); atomicAdd(&qq[c + 1], q1);
        }
    }
    __syncthreads();
    if (tid < 128) {
        atomicAdd(&stats[col0 + tid], ss[tid]);
        atomicAdd(&stats[HIDDEN + col0 + tid], qq[tid]);
    }
}

// ---------------- launch ----------------------------------------------------
extern "C" void kernel_launch(void* const* d_in, const int* in_sizes, int n_in,
                              void* d_out, int out_size) {
    const int*   x     = (const int*)d_in[0];
    const int*   ei    = (const int*)d_in[1];
    const int*   batch = (const int*)d_in[2];
    const float* emb   = (const float*)d_in[3];
    const float* W1    = (const float*)d_in[4];
    const float* g1    = (const float*)d_in[6];
    const float* be1   = (const float*)d_in[7];
    const float* W2    = (const float*)d_in[8];
    const float* g2    = (const float*)d_in[10];
    const float* be2   = (const float*)d_in[11];
    const float* Wl1   = (const float*)d_in[12];
    const float* bl1   = (const float*)d_in[13];
    const float* Wl2   = (const float*)d_in[14];
    const float* bl2   = (const float*)d_in[15];
    float* out = (float*)d_out;

    cudaFuncSetAttribute(k_mma_gemm, cudaFuncAttributeMaxDynamicSharedMemorySize, G_SMEM);

    float *p_h0, *p_agg1, *p_y, *p_h, *p_agg2, *p_stats, *p_coefA, *p_coefB, *p_pooled, *p_cnt;
    __nv_bfloat16 *p_Ahi, *p_Alo, *p_Wthi, *p_Wtlo;
    cudaGetSymbolAddress((void**)&p_h0,    g_h0);
    cudaGetSymbolAddress((void**)&p_agg1,  g_agg1);
    cudaGetSymbolAddress((void**)&p_y,     g_y);
    cudaGetSymbolAddress((void**)&p_h,     g_h);
    cudaGetSymbolAddress((void**)&p_agg2,  g_agg2);
    cudaGetSymbolAddress((void**)&p_stats, g_stats);
    cudaGetSymbolAddress((void**)&p_coefA, g_coefA);
    cudaGetSymbolAddress((void**)&p_coefB, g_coefB);
    cudaGetSymbolAddress((void**)&p_pooled,g_pooled);
    cudaGetSymbolAddress((void**)&p_cnt,   g_cnt);
    cudaGetSymbolAddress((void**)&p_Ahi,   g_Ahi);
    cudaGetSymbolAddress((void**)&p_Alo,   g_Alo);
    cudaGetSymbolAddress((void**)&p_Wthi,  g_Wthi);
    cudaGetSymbolAddress((void**)&p_Wtlo,  g_Wtlo);

    cudaMemsetAsync(p_stats,  0, 4 * HIDDEN * sizeof(float));
    cudaMemsetAsync(p_pooled, 0, (size_t)N_GRAPHS * HIDDEN * sizeof(float));
    cudaMemsetAsync(p_cnt,    0, N_GRAPHS * sizeof(float));

    // ---- embedding + layer-1 aggregation
    k_gather<<<(N_NODES * (EMBED / 4) + 255) / 256, 256>>>(x, emb);
    {
        long long tot = (long long)N_EDGES * (EMBED / 4);
        k_scatter<<<(int)((tot + 255) / 256), 256>>>(ei, p_h0, p_agg1, 6);
    }
    // ---- GEMM1 (fused BN stats)
    {
        long long tot = (long long)ROWSP * (EMBED / 4);
        k_split_A<<<(int)((tot + 255) / 256), 256>>>(p_agg1, N_NODES, 8, p_Ahi, p_Alo);
        k_split_W<<<(HIDDEN * EMBED + 255) / 256, 256>>>(W1, 8, p_Wthi, p_Wtlo);
        dim3 grid(HIDDEN / 128, ROWSP / 128);
        k_mma_gemm<<<grid, GT, G_SMEM>>>(p_Ahi, p_Alo, p_Wthi, p_Wtlo, p_y, p_stats, EMBED);
    }
    k_finalize<<<1, HIDDEN>>>(p_stats, g1, be1, p_coefA, p_coefB);
    {
        long long tot = (long long)N_NODES * (HIDDEN / 4);
        k_norm_relu<<<(int)((tot + 255) / 256), 256>>>(p_y, p_coefA, p_coefB, p_h, p_agg2);
    }

    // ---- layer-2 aggregation
    {
        long long tot = (long long)N_EDGES * (HIDDEN / 4);
        k_scatter<<<(int)((tot + 255) / 256), 256>>>(ei, p_h, p_agg2, 7);
    }
    // ---- GEMM2 (fused BN stats)
    {
        long long tot = (long long)ROWSP * (HIDDEN / 4);
        k_split_A<<<(int)((tot + 255) / 256), 256>>>(p_agg2, N_NODES, 9, p_Ahi, p_Alo);
        k_split_W<<<(HIDDEN * HIDDEN + 255) / 256, 256>>>(W2, 9, p_Wthi, p_Wtlo);
        dim3 grid(HIDDEN / 128, ROWSP / 128);
        k_mma_gemm<<<grid, GT, G_SMEM>>>(p_Ahi, p_Alo, p_Wthi, p_Wtlo, p_y,
                                         p_stats + 2 * HIDDEN, HIDDEN);
    }
    k_finalize<<<1, HIDDEN>>>(p_stats + 2 * HIDDEN, g2, be2,
                              p_coefA + HIDDEN, p_coefB + HIDDEN);

    // ---- pooling (fused layer-2 BN+ReLU) + head
    k_pool_bn<<<(N_NODES + 255) / 256, 512>>>(p_y, batch, p_coefA + HIDDEN, p_coefB + HIDDEN);
    k_lin1<<<N_GRAPHS, HALF_H>>>(Wl1, bl1);
    k_lin2<<<N_GRAPHS, OUT_DIM>>>(Wl2, bl2, out);
}